// round 1
// baseline (speedup 1.0000x reference)
#include <cuda_runtime.h>
#include <math.h>

#define EMBED   1024
#define NHEAD   16
#define HDIM    64
#define BATCH   2
#define SEQ     2048
#define M_TOK   (BATCH*SEQ)        // 4096
#define QSCALE  0.125f             // 1/sqrt(64)

// Scratch (device globals — no allocation allowed)
__device__ float g_qkv[(size_t)M_TOK * 3 * EMBED];   // [tok][3C] packed qkv
__device__ float g_att[(size_t)M_TOK * EMBED];       // attention output [tok][C]

// ---------------------------------------------------------------------------
// Tiled fp32 GEMM with bias:  C[M,N] = A[M,K] @ B[K,N] + bias[N]
// BM=BN=128, BK=16, 256 threads, 8x8 register tile per thread.
// ---------------------------------------------------------------------------
__global__ __launch_bounds__(256) void sgemm_bias(
    const float* __restrict__ A, const float* __restrict__ B,
    const float* __restrict__ bias, float* __restrict__ C,
    int M, int N, int K)
{
    const int BM = 128, BN = 128, BK = 16;
    __shared__ float As[BK][BM];   // transposed A tile
    __shared__ float Bs[BK][BN];

    int tid = threadIdx.x;
    int bm = blockIdx.y * BM;
    int bn = blockIdx.x * BN;
    int tx = tid & 15;        // 0..15 along N
    int ty = tid >> 4;        // 0..15 along M

    int arow  = tid >> 2;           // 0..63
    int acol  = (tid & 3) << 2;     // 0,4,8,12
    int brow  = tid >> 5;           // 0..7
    int bcol  = (tid & 31) << 2;    // 0..124

    float acc[8][8];
    #pragma unroll
    for (int i = 0; i < 8; i++)
        #pragma unroll
        for (int j = 0; j < 8; j++) acc[i][j] = 0.f;

    for (int k0 = 0; k0 < K; k0 += BK) {
        #pragma unroll
        for (int i = 0; i < 2; i++) {
            int r = arow + i * 64;
            float4 v = *(const float4*)(A + (size_t)(bm + r) * K + k0 + acol);
            As[acol + 0][r] = v.x;
            As[acol + 1][r] = v.y;
            As[acol + 2][r] = v.z;
            As[acol + 3][r] = v.w;
        }
        #pragma unroll
        for (int i = 0; i < 2; i++) {
            int r = brow + i * 8;
            *(float4*)&Bs[r][bcol] = *(const float4*)(B + (size_t)(k0 + r) * N + bn + bcol);
        }
        __syncthreads();

        #pragma unroll
        for (int k = 0; k < BK; k++) {
            float a[8], b[8];
            *(float4*)(a + 0) = *(float4*)&As[k][ty * 8 + 0];
            *(float4*)(a + 4) = *(float4*)&As[k][ty * 8 + 4];
            *(float4*)(b + 0) = *(float4*)&Bs[k][tx * 8 + 0];
            *(float4*)(b + 4) = *(float4*)&Bs[k][tx * 8 + 4];
            #pragma unroll
            for (int i = 0; i < 8; i++)
                #pragma unroll
                for (int j = 0; j < 8; j++)
                    acc[i][j] += a[i] * b[j];
        }
        __syncthreads();
    }

    #pragma unroll
    for (int i = 0; i < 8; i++) {
        int r = bm + ty * 8 + i;
        #pragma unroll
        for (int j = 0; j < 8; j += 4) {
            int c = bn + tx * 8 + j;
            float4 v;
            v.x = acc[i][j + 0] + bias[c + 0];
            v.y = acc[i][j + 1] + bias[c + 1];
            v.z = acc[i][j + 2] + bias[c + 2];
            v.w = acc[i][j + 3] + bias[c + 3];
            *(float4*)(C + (size_t)r * N + c) = v;
        }
    }
}

// ---------------------------------------------------------------------------
// Flash-attention style kernel. One block = 64 query rows of one (batch, head).
// 128 threads: thread grid 16 (rows, strided 16) x 8 (cols, strided 8).
// Online softmax stats kept in registers; row reductions via 8-lane shuffles.
// ---------------------------------------------------------------------------
#define AT_BM 64
#define AT_BN 64
#define AT_PAD 4
#define AT_LDS (HDIM + AT_PAD)     // 68

__global__ __launch_bounds__(128) void attn_kernel(
    const float* __restrict__ qkv, float* __restrict__ out)
{
    extern __shared__ float sm[];
    float* Qs = sm;                         // [64][68], pre-scaled by QSCALE
    float* Ks = Qs + AT_BM * AT_LDS;        // [64][68]
    float* Vs = Ks + AT_BN * AT_LDS;        // [64][68]
    float* Ps = Vs + AT_BN * AT_LDS;        // [64][68]  (P tile / staging)

    const int tid = threadIdx.x;
    const int b = blockIdx.z;
    const int h = blockIdx.y;
    const int q0 = blockIdx.x * AT_BM;
    const int gstride = 3 * EMBED;

    const float* qbase = qkv + (size_t)b * SEQ * gstride + h * HDIM;
    const float* kbase = qbase + EMBED;
    const float* vbase = qbase + 2 * EMBED;

    // --- load Q tile (scaled) ---
    {
        int r  = tid >> 1;
        int c4 = (tid & 1) * 8;
        const float4* src = (const float4*)(qbase + (size_t)(q0 + r) * gstride);
        float* drow = Qs + r * AT_LDS;
        #pragma unroll
        for (int i = 0; i < 8; i++) {
            float4 v = src[c4 + i];
            v.x *= QSCALE; v.y *= QSCALE; v.z *= QSCALE; v.w *= QSCALE;
            *(float4*)(drow + (c4 + i) * 4) = v;
        }
    }

    const int tx = tid & 7;    // col group: owns cols tx + 8*j
    const int ty = tid >> 3;   // row group: owns rows ty + 16*i

    float m_i[4], l_i[4], acc_o[4][8];
    #pragma unroll
    for (int i = 0; i < 4; i++) {
        m_i[i] = -1e30f; l_i[i] = 0.f;
        #pragma unroll
        for (int d = 0; d < 8; d++) acc_o[i][d] = 0.f;
    }

    for (int kt = 0; kt < SEQ / AT_BN; kt++) {
        __syncthreads();   // previous iter's smem reads complete (also covers Q load on iter 0)
        // --- load K,V tiles ---
        {
            int r  = tid >> 1;
            int c4 = (tid & 1) * 8;
            const float4* ksrc = (const float4*)(kbase + (size_t)(kt * AT_BN + r) * gstride);
            const float4* vsrc = (const float4*)(vbase + (size_t)(kt * AT_BN + r) * gstride);
            float* kd = Ks + r * AT_LDS;
            float* vd = Vs + r * AT_LDS;
            #pragma unroll
            for (int i = 0; i < 8; i++) {
                *(float4*)(kd + (c4 + i) * 4) = ksrc[c4 + i];
                *(float4*)(vd + (c4 + i) * 4) = vsrc[c4 + i];
            }
        }
        __syncthreads();

        // --- S = (Q*scale) @ K^T ---
        float s[4][8];
        #pragma unroll
        for (int i = 0; i < 4; i++)
            #pragma unroll
            for (int j = 0; j < 8; j++) s[i][j] = 0.f;

        #pragma unroll 8
        for (int d = 0; d < HDIM; d++) {
            float a[4], bb[8];
            #pragma unroll
            for (int i = 0; i < 4; i++) a[i] = Qs[(ty + 16 * i) * AT_LDS + d];
            #pragma unroll
            for (int j = 0; j < 8; j++) bb[j] = Ks[(tx + 8 * j) * AT_LDS + d];
            #pragma unroll
            for (int i = 0; i < 4; i++)
                #pragma unroll
                for (int j = 0; j < 8; j++)
                    s[i][j] += a[i] * bb[j];
        }

        // --- online softmax update (row reductions across 8 lanes sharing a row) ---
        #pragma unroll
        for (int i = 0; i < 4; i++) {
            float mt = s[i][0];
            #pragma unroll
            for (int j = 1; j < 8; j++) mt = fmaxf(mt, s[i][j]);
            mt = fmaxf(mt, __shfl_xor_sync(0xffffffffu, mt, 1));
            mt = fmaxf(mt, __shfl_xor_sync(0xffffffffu, mt, 2));
            mt = fmaxf(mt, __shfl_xor_sync(0xffffffffu, mt, 4));

            float mn = fmaxf(m_i[i], mt);
            float corr = __expf(m_i[i] - mn);
            m_i[i] = mn;

            float rs = 0.f;
            #pragma unroll
            for (int j = 0; j < 8; j++) {
                float p = __expf(s[i][j] - mn);
                s[i][j] = p;
                rs += p;
            }
            rs += __shfl_xor_sync(0xffffffffu, rs, 1);
            rs += __shfl_xor_sync(0xffffffffu, rs, 2);
            rs += __shfl_xor_sync(0xffffffffu, rs, 4);
            l_i[i] = l_i[i] * corr + rs;

            #pragma unroll
            for (int j = 0; j < 8; j++)
                Ps[(ty + 16 * i) * AT_LDS + tx + 8 * j] = s[i][j];
            #pragma unroll
            for (int d = 0; d < 8; d++) acc_o[i][d] *= corr;
        }
        __syncthreads();

        // --- O += P @ V ---
        #pragma unroll 4
        for (int j = 0; j < AT_BN; j++) {
            float a[4], bb[8];
            #pragma unroll
            for (int i = 0; i < 4; i++) a[i] = Ps[(ty + 16 * i) * AT_LDS + j];
            #pragma unroll
            for (int d = 0; d < 8; d++) bb[d] = Vs[j * AT_LDS + tx + 8 * d];
            #pragma unroll
            for (int i = 0; i < 4; i++)
                #pragma unroll
                for (int d = 0; d < 8; d++)
                    acc_o[i][d] += a[i] * bb[d];
        }
    }

    __syncthreads();
    // --- normalize, stage through smem, coalesced store ---
    #pragma unroll
    for (int i = 0; i < 4; i++) {
        float inv = 1.f / l_i[i];
        #pragma unroll
        for (int d = 0; d < 8; d++)
            Ps[(ty + 16 * i) * AT_LDS + tx + 8 * d] = acc_o[i][d] * inv;
    }
    __syncthreads();
    {
        int r  = tid >> 1;
        int c4 = (tid & 1) * 8;
        float* dst = out + (size_t)(b * SEQ + q0 + r) * EMBED + h * HDIM;
        const float* srow = Ps + r * AT_LDS;
        #pragma unroll
        for (int i = 0; i < 8; i++)
            *(float4*)(dst + (c4 + i) * 4) = *(const float4*)(srow + (c4 + i) * 4);
    }
}

// ---------------------------------------------------------------------------
extern "C" void kernel_launch(void* const* d_in, const int* in_sizes, int n_in,
                              void* d_out, int out_size)
{
    const float* x     = (const float*)d_in[0];   // [2,2048,1024]
    const float* Wqkv  = (const float*)d_in[1];   // [1024,3072]
    const float* bqkv  = (const float*)d_in[2];   // [3072]
    const float* Wproj = (const float*)d_in[3];   // [1024,1024]
    const float* bproj = (const float*)d_in[4];   // [1024]
    float* out = (float*)d_out;                   // [2,2048,1024]

    float *qkv_ptr, *att_ptr;
    cudaGetSymbolAddress((void**)&qkv_ptr, g_qkv);
    cudaGetSymbolAddress((void**)&att_ptr, g_att);

    // 1) QKV projection: [4096,1024] @ [1024,3072] + b
    {
        dim3 grid(3 * EMBED / 128, M_TOK / 128);
        sgemm_bias<<<grid, 256>>>(x, Wqkv, bqkv, qkv_ptr, M_TOK, 3 * EMBED, EMBED);
    }

    // 2) Attention
    {
        size_t smem = (size_t)4 * AT_BM * AT_LDS * sizeof(float);  // 69,632 B
        cudaFuncSetAttribute(attn_kernel,
                             cudaFuncAttributeMaxDynamicSharedMemorySize, (int)smem);
        dim3 grid(SEQ / AT_BM, NHEAD, BATCH);
        attn_kernel<<<grid, 128, smem>>>(qkv_ptr, att_ptr);
    }

    // 3) Output projection: [4096,1024] @ [1024,1024] + b
    {
        dim3 grid(EMBED / 128, M_TOK / 128);
        sgemm_bias<<<grid, 256>>>(att_ptr, Wproj, bproj, out, M_TOK, EMBED, EMBED);
    }
}